// round 2
// baseline (speedup 1.0000x reference)
#include <cuda_runtime.h>

typedef unsigned long long ull;

#define NCTA 128          // scan grid: one CTA per 8 H-columns
#define SMEM_WS_ULL (12 * 1026)           // 3 gates x 4 jpairs, row 1026 ull (pad)
#define SMEM_HS_OFF (SMEM_WS_ULL * 8)     // bytes
#define SCAN_SMEM   (SMEM_HS_OFF + 64 * 132 * 4)   // + h chunk [64][132] floats

// ---------------- device scratch (allocation-free contract) -----------------
__device__ float g_EW[128 * 3 * 1024];    // EW[v][g][j] includes input bias
__device__ float g_Wc[1024 * 128];        // Wh @ Wo
__device__ float g_bc[128];               // bh @ Wo + bo
__device__ float g_h[2 * 64 * 1024];      // ping-pong hidden state
__device__ float g_y[64u * 512u * 1024u]; // all hidden states [b][t][j]
__device__ unsigned g_cnt;
__device__ volatile unsigned g_gen;

// ---------------- f32x2 helpers ---------------------------------------------
__device__ __forceinline__ ull fma2(ull a, ull b, ull c) {
    ull d;
    asm("fma.rn.f32x2 %0, %1, %2, %3;" : "=l"(d) : "l"(a), "l"(b), "l"(c));
    return d;
}
__device__ __forceinline__ ull dup2(float x) {
    ull r; unsigned u = __float_as_uint(x);
    asm("mov.b64 %0, {%1, %1};" : "=l"(r) : "r"(u));
    return r;
}
__device__ __forceinline__ ull pack2(float lo, float hi) {
    ull r;
    asm("mov.b64 %0, {%1, %2};" : "=l"(r) : "r"(__float_as_uint(lo)), "r"(__float_as_uint(hi)));
    return r;
}
__device__ __forceinline__ float2 unpk2(ull v) {
    unsigned lo, hi;
    asm("mov.b64 {%0, %1}, %2;" : "=r"(lo), "=r"(hi) : "l"(v));
    return make_float2(__uint_as_float(lo), __uint_as_float(hi));
}

// ---------------- prep: EW table --------------------------------------------
__global__ __launch_bounds__(256) void prep_ew(
    const float* __restrict__ emb,
    const float* __restrict__ Wir, const float* __restrict__ bir,
    const float* __restrict__ Wiz, const float* __restrict__ biz,
    const float* __restrict__ Win, const float* __restrict__ bin_)
{
    __shared__ float se[128];
    int v = blockIdx.x, tid = threadIdx.x;
    if (tid < 128) se[tid] = emb[v * 128 + tid];
    __syncthreads();
    for (int i = tid; i < 3072; i += 256) {
        int g = i >> 10, j = i & 1023;
        const float* W  = (g == 0) ? Wir : (g == 1) ? Wiz : Win;
        const float* bb = (g == 0) ? bir : (g == 1) ? biz : bin_;
        float acc = bb[j];
        #pragma unroll 8
        for (int e = 0; e < 128; ++e) acc += se[e] * W[e * 1024 + j];
        g_EW[v * 3072 + i] = acc;
    }
}

// ---------------- prep: carry copy + bc + barrier reset ---------------------
__global__ __launch_bounds__(256) void prep_misc(
    const float* __restrict__ carry, const float* __restrict__ bh,
    const float* __restrict__ Wo,    const float* __restrict__ bo)
{
    int bx = blockIdx.x, tid = threadIdx.x;
    if (bx < 64) {
        ((float4*)g_h)[bx * 256 + tid] = ((const float4*)carry)[bx * 256 + tid];
    } else {
        if (tid < 128) {
            float acc = bo[tid];
            for (int m = 0; m < 1024; ++m) acc += bh[m] * Wo[m * 128 + tid];
            g_bc[tid] = acc;
        }
        if (tid == 0) { g_cnt = 0u; g_gen = 0u; }
    }
}

// ---------------- tiled GEMM: C[M x 128] = A[M x 1024] @ B[1024 x 128] + bias
__global__ __launch_bounds__(256) void gemm128(
    const float* __restrict__ A, const float* __restrict__ Bm,
    const float* __restrict__ bias, float* __restrict__ C)
{
    __shared__ float As[32][132];   // [k][m], transposed
    __shared__ float Bs[32][128];   // [k][n]
    int tid = threadIdx.x;
    int tx = tid & 15, ty = tid >> 4;       // n-group, m-group
    int m0 = blockIdx.x * 128;

    float acc[8][8];
    #pragma unroll
    for (int i = 0; i < 8; ++i)
        #pragma unroll
        for (int j = 0; j < 8; ++j)
            acc[i][j] = bias ? bias[tx * 8 + j] : 0.0f;

    for (int k0 = 0; k0 < 1024; k0 += 32) {
        __syncthreads();
        #pragma unroll
        for (int i = 0; i < 4; ++i) {   // A tile, transpose into As[k][m]
            int idx = tid + i * 256;
            int m = idx >> 3, q = idx & 7;
            float4 v = *(const float4*)(A + (size_t)(m0 + m) * 1024 + k0 + q * 4);
            As[q * 4 + 0][m] = v.x; As[q * 4 + 1][m] = v.y;
            As[q * 4 + 2][m] = v.z; As[q * 4 + 3][m] = v.w;
        }
        #pragma unroll
        for (int i = 0; i < 4; ++i) {   // B tile, direct
            int idx = tid + i * 256;
            int r = idx >> 5, q = idx & 31;
            *(float4*)(&Bs[r][q * 4]) = *(const float4*)(Bm + (size_t)(k0 + r) * 128 + q * 4);
        }
        __syncthreads();
        #pragma unroll 4
        for (int kk = 0; kk < 32; ++kk) {
            float4 a0 = *(const float4*)(&As[kk][ty * 8]);
            float4 a1 = *(const float4*)(&As[kk][ty * 8 + 4]);
            float4 b0 = *(const float4*)(&Bs[kk][tx * 8]);
            float4 b1 = *(const float4*)(&Bs[kk][tx * 8 + 4]);
            float av[8] = {a0.x, a0.y, a0.z, a0.w, a1.x, a1.y, a1.z, a1.w};
            float bv[8] = {b0.x, b0.y, b0.z, b0.w, b1.x, b1.y, b1.z, b1.w};
            #pragma unroll
            for (int i = 0; i < 8; ++i)
                #pragma unroll
                for (int j = 0; j < 8; ++j)
                    acc[i][j] = fmaf(av[i], bv[j], acc[i][j]);
        }
    }
    #pragma unroll
    for (int i = 0; i < 8; ++i) {
        float* cp = C + (size_t)(m0 + ty * 8 + i) * 128 + tx * 8;
        *(float4*)cp       = make_float4(acc[i][0], acc[i][1], acc[i][2], acc[i][3]);
        *(float4*)(cp + 4) = make_float4(acc[i][4], acc[i][5], acc[i][6], acc[i][7]);
    }
}

// ---------------- persistent GRU scan ---------------------------------------
__global__ __launch_bounds__(256, 1) void scan_kernel(
    const int*   __restrict__ toks,
    const float* __restrict__ Whr, const float* __restrict__ Whz,
    const float* __restrict__ Whn, const float* __restrict__ bhn)
{
    extern __shared__ char smbase[];
    ull*   ws = (ull*)smbase;                      // [12][1026] (gate*4+jp rows)
    float* hs = (float*)(smbase + SMEM_HS_OFF);    // [64][132]

    const int tid = threadIdx.x, bx = blockIdx.x;
    const int l = tid & 31, w = tid >> 5;
    const int b  = w * 8 + (l & 7);    // warp owns 8 batches
    const int jp = l >> 3;             // 4 j-pairs per warp
    const int jbase = bx * 8;
    const int j0 = jbase + jp * 2;

    // ---- load recurrent weights into smem once (pairs over j) ----
    for (int i = tid; i < 3 * 1024; i += 256) {
        int g = i >> 10, k = i & 1023;
        const float* Wg = (g == 0) ? Whr : (g == 1) ? Whz : Whn;
        float4 v0 = *(const float4*)(Wg + (size_t)k * 1024 + jbase);
        float4 v1 = *(const float4*)(Wg + (size_t)k * 1024 + jbase + 4);
        *(float2*)(ws + (g * 4 + 0) * 1026 + k) = make_float2(v0.x, v0.y);
        *(float2*)(ws + (g * 4 + 1) * 1026 + k) = make_float2(v0.z, v0.w);
        *(float2*)(ws + (g * 4 + 2) * 1026 + k) = make_float2(v1.x, v1.y);
        *(float2*)(ws + (g * 4 + 3) * 1026 + k) = make_float2(v1.z, v1.w);
    }
    const ull* wr = ws + (0 + jp) * 1026;
    const ull* wz = ws + (4 + jp) * 1026;
    const ull* wn = ws + (8 + jp) * 1026;
    const float* hrow = hs + b * 132;
    float2 bhn2 = *(const float2*)(bhn + j0);
    __syncthreads();

    float4 pf[8];
    for (int t = 0; t < 512; ++t) {
        const int p = t & 1;
        const float* hsrc = g_h + p * 65536;
        float*       hdst = g_h + (p ^ 1) * 65536;

        const int tok = toks[(b << 9) + t];
        const float* ewp = g_EW + tok * 3072;
        ull acc_r = pack2(ewp[j0], ewp[j0 + 1]);
        ull acc_z = pack2(ewp[1024 + j0], ewp[1024 + j0 + 1]);
        float2 ewn = *(const float2*)(ewp + 2048 + j0);
        ull acc_n = pack2(bhn2.x, bhn2.y);
        float2 hold = *(const float2*)(hsrc + b * 1024 + j0);

        const float4* src4 = (const float4*)hsrc;
        #pragma unroll
        for (int i = 0; i < 8; ++i) {            // prefetch chunk 0
            int idx = tid + (i << 8);
            pf[i] = src4[((idx >> 5) << 8) + (idx & 31)];
        }

        for (int c = 0; c < 8; ++c) {
            __syncthreads();                      // prior compute done with hs
            #pragma unroll
            for (int i = 0; i < 8; ++i) {         // stage chunk c
                int idx = tid + (i << 8);
                int bb = idx >> 5, q = idx & 31;
                *(float4*)(hs + bb * 132 + q * 4) = pf[i];
            }
            __syncthreads();
            if (c < 7) {
                #pragma unroll
                for (int i = 0; i < 8; ++i) {     // prefetch chunk c+1
                    int idx = tid + (i << 8);
                    pf[i] = src4[((idx >> 5) << 8) + ((c + 1) << 5) + (idx & 31)];
                }
            }
            const int kb = c << 7;
            #pragma unroll 4
            for (int kk = 0; kk < 128; kk += 4) {
                float4 hv = *(const float4*)(hrow + kk);
                ull hx = dup2(hv.x), hy = dup2(hv.y), hz = dup2(hv.z), hw = dup2(hv.w);
                int k = kb + kk;
                ulonglong2 r01 = *(const ulonglong2*)(wr + k);
                ulonglong2 r23 = *(const ulonglong2*)(wr + k + 2);
                ulonglong2 z01 = *(const ulonglong2*)(wz + k);
                ulonglong2 z23 = *(const ulonglong2*)(wz + k + 2);
                ulonglong2 n01 = *(const ulonglong2*)(wn + k);
                ulonglong2 n23 = *(const ulonglong2*)(wn + k + 2);
                acc_r = fma2(hx, r01.x, acc_r); acc_r = fma2(hy, r01.y, acc_r);
                acc_r = fma2(hz, r23.x, acc_r); acc_r = fma2(hw, r23.y, acc_r);
                acc_z = fma2(hx, z01.x, acc_z); acc_z = fma2(hy, z01.y, acc_z);
                acc_z = fma2(hz, z23.x, acc_z); acc_z = fma2(hw, z23.y, acc_z);
                acc_n = fma2(hx, n01.x, acc_n); acc_n = fma2(hy, n01.y, acc_n);
                acc_n = fma2(hz, n23.x, acc_n); acc_n = fma2(hw, n23.y, acc_n);
            }
        }

        // ---- gate nonlinearities + state update ----
        float2 ar = unpk2(acc_r), az = unpk2(acc_z), an = unpk2(acc_n);
        float r0 = 1.0f / (1.0f + expf(-ar.x)), r1 = 1.0f / (1.0f + expf(-ar.y));
        float z0 = 1.0f / (1.0f + expf(-az.x)), z1 = 1.0f / (1.0f + expf(-az.y));
        float n0 = tanhf(ewn.x + r0 * an.x);
        float n1 = tanhf(ewn.y + r1 * an.y);
        float h0 = (1.0f - z0) * n0 + z0 * hold.x;
        float h1 = (1.0f - z1) * n1 + z1 * hold.y;
        float2 hv2 = make_float2(h0, h1);
        *(float2*)(hdst + b * 1024 + j0) = hv2;
        *(float2*)(g_y + (size_t)((b << 9) + t) * 1024 + j0) = hv2;

        // ---- grid barrier ----
        __threadfence();
        __syncthreads();
        if (tid == 0) {
            if (atomicAdd(&g_cnt, 1u) == (unsigned)(NCTA - 1)) {
                g_cnt = 0u;
                __threadfence();
                g_gen = (unsigned)(t + 1);
            } else {
                while (g_gen < (unsigned)(t + 1)) { }
            }
        }
        __syncthreads();
    }
}

// ---------------- carry_out copy --------------------------------------------
__global__ __launch_bounds__(256) void copy_carry(float* __restrict__ out)
{
    ((float4*)out)[blockIdx.x * 256 + threadIdx.x] =
        ((const float4*)g_h)[blockIdx.x * 256 + threadIdx.x];
}

// ---------------- launch ----------------------------------------------------
extern "C" void kernel_launch(void* const* d_in, const int* in_sizes, int n_in,
                              void* d_out, int out_size)
{
    const int*   toks  = (const int*)  d_in[0];
    const float* carry = (const float*)d_in[1];
    const float* emb   = (const float*)d_in[2];
    const float* Wir   = (const float*)d_in[3];
    const float* bir   = (const float*)d_in[4];
    const float* Whr   = (const float*)d_in[5];
    const float* Wiz   = (const float*)d_in[6];
    const float* biz   = (const float*)d_in[7];
    const float* Whz   = (const float*)d_in[8];
    const float* Win   = (const float*)d_in[9];
    const float* bin_  = (const float*)d_in[10];
    const float* Whn   = (const float*)d_in[11];
    const float* bhn   = (const float*)d_in[12];
    const float* Wh    = (const float*)d_in[13];
    const float* bh    = (const float*)d_in[14];
    const float* Wo    = (const float*)d_in[15];
    const float* bo    = (const float*)d_in[16];
    float* out = (float*)d_out;

    void *pY = 0, *pWc = 0, *pbc = 0;
    cudaGetSymbolAddress(&pY,  g_y);
    cudaGetSymbolAddress(&pWc, g_Wc);
    cudaGetSymbolAddress(&pbc, g_bc);

    cudaFuncSetAttribute(scan_kernel, cudaFuncAttributeMaxDynamicSharedMemorySize, SCAN_SMEM);

    prep_ew<<<128, 256>>>(emb, Wir, bir, Wiz, biz, Win, bin_);
    gemm128<<<8, 256>>>(Wh, Wo, (const float*)0, (float*)pWc);   // Wc = Wh @ Wo
    prep_misc<<<65, 256>>>(carry, bh, Wo, bo);
    scan_kernel<<<NCTA, 256, SCAN_SMEM>>>(toks, Whr, Whz, Whn, bhn);
    copy_carry<<<64, 256>>>(out);
    gemm128<<<256, 256>>>((const float*)pY, (const float*)pWc, (const float*)pbc,
                          out + 65536);                           // logits
}

// round 3
// speedup vs baseline: 1.0378x; 1.0378x over previous
#include <cuda_runtime.h>

typedef unsigned long long ull;

#define NCTA 128
#define WS_BYTES (12 * 1026 * 8)                  // weights: ull[12][1026]
#define HBUF_FLOATS (64 * 66)                     // one h buffer [64][66]
#define SCAN_SMEM (WS_BYTES + 4 * HBUF_FLOATS * 4)

// ---------------- device scratch (allocation-free contract) -----------------
__device__ float g_EW[128 * 3 * 1024];    // EW[v][g][j] includes input bias
__device__ float g_Wc[1024 * 128];        // Wh @ Wo
__device__ float g_bc[128];               // bh @ Wo + bo
__device__ float g_h[2 * 64 * 1024];      // ping-pong hidden state
__device__ float g_y[64u * 512u * 1024u]; // all hidden states [b][t][j]
__device__ unsigned g_cnt;
__device__ volatile unsigned g_gen;

// ---------------- f32x2 helpers ---------------------------------------------
__device__ __forceinline__ ull fma2(ull a, ull b, ull c) {
    ull d;
    asm("fma.rn.f32x2 %0, %1, %2, %3;" : "=l"(d) : "l"(a), "l"(b), "l"(c));
    return d;
}
__device__ __forceinline__ ull add2(ull a, ull b) {
    ull d;
    asm("add.rn.f32x2 %0, %1, %2;" : "=l"(d) : "l"(a), "l"(b));
    return d;
}
__device__ __forceinline__ ull dup2(float x) {
    ull r; unsigned u = __float_as_uint(x);
    asm("mov.b64 %0, {%1, %1};" : "=l"(r) : "r"(u));
    return r;
}
__device__ __forceinline__ float2 unpk2(ull v) {
    unsigned lo, hi;
    asm("mov.b64 {%0, %1}, %2;" : "=r"(lo), "=r"(hi) : "l"(v));
    return make_float2(__uint_as_float(lo), __uint_as_float(hi));
}

// ---------------- prep: EW table --------------------------------------------
__global__ __launch_bounds__(256) void prep_ew(
    const float* __restrict__ emb,
    const float* __restrict__ Wir, const float* __restrict__ bir,
    const float* __restrict__ Wiz, const float* __restrict__ biz,
    const float* __restrict__ Win, const float* __restrict__ bin_)
{
    __shared__ float se[128];
    int v = blockIdx.x, tid = threadIdx.x;
    if (tid < 128) se[tid] = emb[v * 128 + tid];
    __syncthreads();
    for (int i = tid; i < 3072; i += 256) {
        int g = i >> 10, j = i & 1023;
        const float* W  = (g == 0) ? Wir : (g == 1) ? Wiz : Win;
        const float* bb = (g == 0) ? bir : (g == 1) ? biz : bin_;
        float acc = bb[j];
        #pragma unroll 8
        for (int e = 0; e < 128; ++e) acc += se[e] * W[e * 1024 + j];
        g_EW[v * 3072 + i] = acc;
    }
}

// ---------------- prep: carry copy + bc + barrier reset ---------------------
__global__ __launch_bounds__(256) void prep_misc(
    const float* __restrict__ carry, const float* __restrict__ bh,
    const float* __restrict__ Wo,    const float* __restrict__ bo)
{
    int bx = blockIdx.x, tid = threadIdx.x;
    if (bx < 64) {
        ((float4*)g_h)[bx * 256 + tid] = ((const float4*)carry)[bx * 256 + tid];
    } else {
        if (tid < 128) {
            float acc = bo[tid];
            for (int m = 0; m < 1024; ++m) acc += bh[m] * Wo[m * 128 + tid];
            g_bc[tid] = acc;
        }
        if (tid == 0) { g_cnt = 0u; g_gen = 0u; }
    }
}

// ---------------- tiled GEMM: C[M x 128] = A[M x 1024] @ B[1024 x 128] + bias
__global__ __launch_bounds__(256) void gemm128(
    const float* __restrict__ A, const float* __restrict__ Bm,
    const float* __restrict__ bias, float* __restrict__ C)
{
    __shared__ float As[32][132];   // [k][m], transposed
    __shared__ float Bs[32][128];   // [k][n]
    int tid = threadIdx.x;
    int tx = tid & 15, ty = tid >> 4;
    int m0 = blockIdx.x * 128;

    float acc[8][8];
    #pragma unroll
    for (int i = 0; i < 8; ++i)
        #pragma unroll
        for (int j = 0; j < 8; ++j)
            acc[i][j] = bias ? bias[tx * 8 + j] : 0.0f;

    for (int k0 = 0; k0 < 1024; k0 += 32) {
        __syncthreads();
        #pragma unroll
        for (int i = 0; i < 4; ++i) {
            int idx = tid + i * 256;
            int m = idx >> 3, q = idx & 7;
            float4 v = *(const float4*)(A + (size_t)(m0 + m) * 1024 + k0 + q * 4);
            As[q * 4 + 0][m] = v.x; As[q * 4 + 1][m] = v.y;
            As[q * 4 + 2][m] = v.z; As[q * 4 + 3][m] = v.w;
        }
        #pragma unroll
        for (int i = 0; i < 4; ++i) {
            int idx = tid + i * 256;
            int r = idx >> 5, q = idx & 31;
            *(float4*)(&Bs[r][q * 4]) = *(const float4*)(Bm + (size_t)(k0 + r) * 128 + q * 4);
        }
        __syncthreads();
        #pragma unroll 4
        for (int kk = 0; kk < 32; ++kk) {
            float4 a0 = *(const float4*)(&As[kk][ty * 8]);
            float4 a1 = *(const float4*)(&As[kk][ty * 8 + 4]);
            float4 b0 = *(const float4*)(&Bs[kk][tx * 8]);
            float4 b1 = *(const float4*)(&Bs[kk][tx * 8 + 4]);
            float av[8] = {a0.x, a0.y, a0.z, a0.w, a1.x, a1.y, a1.z, a1.w};
            float bv[8] = {b0.x, b0.y, b0.z, b0.w, b1.x, b1.y, b1.z, b1.w};
            #pragma unroll
            for (int i = 0; i < 8; ++i)
                #pragma unroll
                for (int j = 0; j < 8; ++j)
                    acc[i][j] = fmaf(av[i], bv[j], acc[i][j]);
        }
    }
    #pragma unroll
    for (int i = 0; i < 8; ++i) {
        float* cp = C + (size_t)(m0 + ty * 8 + i) * 128 + tx * 8;
        *(float4*)cp       = make_float4(acc[i][0], acc[i][1], acc[i][2], acc[i][3]);
        *(float4*)(cp + 4) = make_float4(acc[i][4], acc[i][5], acc[i][6], acc[i][7]);
    }
}

// ---------------- persistent GRU scan (512 thr, 4-way k-split) --------------
__global__ __launch_bounds__(512, 1) void scan_kernel(
    const int*   __restrict__ toks,
    const float* __restrict__ Whr, const float* __restrict__ Whz,
    const float* __restrict__ Whn, const float* __restrict__ bhn)
{
    extern __shared__ char smbase[];
    ull*   ws = (ull*)smbase;                      // [12][1026]
    float* hs = (float*)(smbase + WS_BYTES);       // 4 x [64][66]

    const int tid = threadIdx.x, bx = blockIdx.x;
    const int kh = tid >> 7;                 // k-quarter 0..3
    const int r  = tid & 127;
    const int b2 = r >> 2;                   // batch pair 0..31
    const int jp = r & 3;                    // j-pair 0..3
    const int be = 2 * b2, bo = be + 1;
    const int jbase = bx * 8;
    const int j0 = jbase + jp * 2;

    // ---- load recurrent weights into smem once (pairs over j) ----
    for (int i = tid; i < 3 * 1024; i += 512) {
        int g = i >> 10, k = i & 1023;
        const float* Wg = (g == 0) ? Whr : (g == 1) ? Whz : Whn;
        float4 v0 = *(const float4*)(Wg + (size_t)k * 1024 + jbase);
        float4 v1 = *(const float4*)(Wg + (size_t)k * 1024 + jbase + 4);
        *(float2*)(ws + (g * 4 + 0) * 1026 + k) = make_float2(v0.x, v0.y);
        *(float2*)(ws + (g * 4 + 1) * 1026 + k) = make_float2(v0.z, v0.w);
        *(float2*)(ws + (g * 4 + 2) * 1026 + k) = make_float2(v1.x, v1.y);
        *(float2*)(ws + (g * 4 + 3) * 1026 + k) = make_float2(v1.z, v1.w);
    }
    const ull* wr = ws + (0 + jp) * 1026;
    const ull* wz = ws + (4 + jp) * 1026;
    const ull* wn = ws + (8 + jp) * 1026;
    const float* hb      = hs + kh * HBUF_FLOATS;
    const float* hrow_e  = hb + be * 66;
    const float* hrow_o  = hb + bo * 66;
    const float2 bhn2 = *(const float2*)(bhn + j0);
    __syncthreads();

    float4 pf[8];
    for (int t = 0; t < 512; ++t) {
        const int p = t & 1;
        const float* hsrc = g_h + p * 65536;
        float*       hdst = g_h + (p ^ 1) * 65536;

        int tok_e = 0, tok_o = 0;
        if (kh == 0) {                      // finisher threads: early token loads
            tok_e = toks[(be << 9) + t];
            tok_o = toks[(bo << 9) + t];
        }

        // prefetch phase-0 staging data
        #pragma unroll
        for (int i = 0; i < 8; ++i) {
            int f = tid + (i << 9);
            int q = f >> 10, rem = f & 1023, b = rem >> 4, kq = rem & 15;
            pf[i] = *(const float4*)(hsrc + b * 1024 + q * 256 + kq * 4);
        }

        ull accr_e = 0, accz_e = 0, accn_e = 0;
        ull accr_o = 0, accz_o = 0, accn_o = 0;

        for (int ph = 0; ph < 4; ++ph) {
            __syncthreads();                 // prior compute done with buffers
            #pragma unroll
            for (int i = 0; i < 8; ++i) {    // stage all 4 kh-buffers
                int f = tid + (i << 9);
                int q = f >> 10, rem = f & 1023, b = rem >> 4, kq = rem & 15;
                float* dst = hs + q * HBUF_FLOATS + b * 66 + kq * 4;
                *(float2*)dst       = make_float2(pf[i].x, pf[i].y);
                *(float2*)(dst + 2) = make_float2(pf[i].z, pf[i].w);
            }
            __syncthreads();
            if (ph < 3) {
                #pragma unroll
                for (int i = 0; i < 8; ++i) {   // prefetch next phase
                    int f = tid + (i << 9);
                    int q = f >> 10, rem = f & 1023, b = rem >> 4, kq = rem & 15;
                    pf[i] = *(const float4*)(hsrc + b * 1024 + q * 256 + (ph + 1) * 64 + kq * 4);
                }
            }
            const int kb = (kh << 8) + (ph << 6);
            #pragma unroll 2
            for (int kk = 0; kk < 64; kk += 4) {
                const int k = kb + kk;
                float2 e01 = *(const float2*)(hrow_e + kk);
                float2 e23 = *(const float2*)(hrow_e + kk + 2);
                float2 o01 = *(const float2*)(hrow_o + kk);
                float2 o23 = *(const float2*)(hrow_o + kk + 2);
                ulonglong2 r01 = *(const ulonglong2*)(wr + k);
                ulonglong2 r23 = *(const ulonglong2*)(wr + k + 2);
                ulonglong2 z01 = *(const ulonglong2*)(wz + k);
                ulonglong2 z23 = *(const ulonglong2*)(wz + k + 2);
                ulonglong2 n01 = *(const ulonglong2*)(wn + k);
                ulonglong2 n23 = *(const ulonglong2*)(wn + k + 2);
                ull ex = dup2(e01.x), ey = dup2(e01.y), ez = dup2(e23.x), ew2 = dup2(e23.y);
                ull ox = dup2(o01.x), oy = dup2(o01.y), oz = dup2(o23.x), ow2 = dup2(o23.y);
                accr_e = fma2(ex, r01.x, accr_e); accr_e = fma2(ey, r01.y, accr_e);
                accr_e = fma2(ez, r23.x, accr_e); accr_e = fma2(ew2, r23.y, accr_e);
                accz_e = fma2(ex, z01.x, accz_e); accz_e = fma2(ey, z01.y, accz_e);
                accz_e = fma2(ez, z23.x, accz_e); accz_e = fma2(ew2, z23.y, accz_e);
                accn_e = fma2(ex, n01.x, accn_e); accn_e = fma2(ey, n01.y, accn_e);
                accn_e = fma2(ez, n23.x, accn_e); accn_e = fma2(ew2, n23.y, accn_e);
                accr_o = fma2(ox, r01.x, accr_o); accr_o = fma2(oy, r01.y, accr_o);
                accr_o = fma2(oz, r23.x, accr_o); accr_o = fma2(ow2, r23.y, accr_o);
                accz_o = fma2(ox, z01.x, accz_o); accz_o = fma2(oy, z01.y, accz_o);
                accz_o = fma2(oz, z23.x, accz_o); accz_o = fma2(ow2, z23.y, accz_o);
                accn_o = fma2(ox, n01.x, accn_o); accn_o = fma2(oy, n01.y, accn_o);
                accn_o = fma2(oz, n23.x, accn_o); accn_o = fma2(ow2, n23.y, accn_o);
            }
        }

        // ---- cross-kh reduction via smem ----
        __syncthreads();
        ull* red = (ull*)hs;
        {
            ulonglong2* mp = (ulonglong2*)(red + tid * 6);
            mp[0] = make_ulonglong2(accr_e, accr_o);
            mp[1] = make_ulonglong2(accz_e, accz_o);
            mp[2] = make_ulonglong2(accn_e, accn_o);
        }
        __syncthreads();
        if (kh == 0) {
            ull Ar_e = accr_e, Ar_o = accr_o;
            ull Az_e = accz_e, Az_o = accz_o;
            ull An_e = accn_e, An_o = accn_o;
            #pragma unroll
            for (int q2 = 1; q2 < 4; ++q2) {
                const ulonglong2* pp = (const ulonglong2*)(red + (tid + (q2 << 7)) * 6);
                ulonglong2 a = pp[0], bq = pp[1], c = pp[2];
                Ar_e = add2(Ar_e, a.x);  Ar_o = add2(Ar_o, a.y);
                Az_e = add2(Az_e, bq.x); Az_o = add2(Az_o, bq.y);
                An_e = add2(An_e, c.x);  An_o = add2(An_o, c.y);
            }
            const float* ewp_e = g_EW + tok_e * 3072;
            const float* ewp_o = g_EW + tok_o * 3072;
            float2 ewr_e = *(const float2*)(ewp_e + j0);
            float2 ewz_e = *(const float2*)(ewp_e + 1024 + j0);
            float2 ewn_e = *(const float2*)(ewp_e + 2048 + j0);
            float2 ewr_o = *(const float2*)(ewp_o + j0);
            float2 ewz_o = *(const float2*)(ewp_o + 1024 + j0);
            float2 ewn_o = *(const float2*)(ewp_o + 2048 + j0);
            float2 hold_e = *(const float2*)(hsrc + be * 1024 + j0);
            float2 hold_o = *(const float2*)(hsrc + bo * 1024 + j0);

            float2 sre = unpk2(Ar_e), sze = unpk2(Az_e), sne = unpk2(An_e);
            float r0 = 1.0f / (1.0f + expf(-(ewr_e.x + sre.x)));
            float r1 = 1.0f / (1.0f + expf(-(ewr_e.y + sre.y)));
            float z0 = 1.0f / (1.0f + expf(-(ewz_e.x + sze.x)));
            float z1 = 1.0f / (1.0f + expf(-(ewz_e.y + sze.y)));
            float n0 = tanhf(ewn_e.x + r0 * (sne.x + bhn2.x));
            float n1 = tanhf(ewn_e.y + r1 * (sne.y + bhn2.y));
            float2 hv_e = make_float2((1.0f - z0) * n0 + z0 * hold_e.x,
                                      (1.0f - z1) * n1 + z1 * hold_e.y);

            float2 sro = unpk2(Ar_o), szo = unpk2(Az_o), sno = unpk2(An_o);
            float q0 = 1.0f / (1.0f + expf(-(ewr_o.x + sro.x)));
            float q1 = 1.0f / (1.0f + expf(-(ewr_o.y + sro.y)));
            float y0 = 1.0f / (1.0f + expf(-(ewz_o.x + szo.x)));
            float y1 = 1.0f / (1.0f + expf(-(ewz_o.y + szo.y)));
            float m0 = tanhf(ewn_o.x + q0 * (sno.x + bhn2.x));
            float m1 = tanhf(ewn_o.y + q1 * (sno.y + bhn2.y));
            float2 hv_o = make_float2((1.0f - y0) * m0 + y0 * hold_o.x,
                                      (1.0f - y1) * m1 + y1 * hold_o.y);

            *(float2*)(hdst + be * 1024 + j0) = hv_e;
            *(float2*)(hdst + bo * 1024 + j0) = hv_o;
            *(float2*)(g_y + (size_t)((be << 9) + t) * 1024 + j0) = hv_e;
            *(float2*)(g_y + (size_t)((bo << 9) + t) * 1024 + j0) = hv_o;
        }

        // ---- grid barrier ----
        __threadfence();
        __syncthreads();
        if (tid == 0) {
            if (atomicAdd(&g_cnt, 1u) == (unsigned)(NCTA - 1)) {
                g_cnt = 0u;
                __threadfence();
                g_gen = (unsigned)(t + 1);
            } else {
                while (g_gen < (unsigned)(t + 1)) { }
            }
        }
        __syncthreads();
    }
}

// ---------------- carry_out copy --------------------------------------------
__global__ __launch_bounds__(256) void copy_carry(float* __restrict__ out)
{
    ((float4*)out)[blockIdx.x * 256 + threadIdx.x] =
        ((const float4*)g_h)[blockIdx.x * 256 + threadIdx.x];
}

// ---------------- launch ----------------------------------------------------
extern "C" void kernel_launch(void* const* d_in, const int* in_sizes, int n_in,
                              void* d_out, int out_size)
{
    const int*   toks  = (const int*)  d_in[0];
    const float* carry = (const float*)d_in[1];
    const float* emb   = (const float*)d_in[2];
    const float* Wir   = (const float*)d_in[3];
    const float* bir   = (const float*)d_in[4];
    const float* Whr   = (const float*)d_in[5];
    const float* Wiz   = (const float*)d_in[6];
    const float* biz   = (const float*)d_in[7];
    const float* Whz   = (const float*)d_in[8];
    const float* Win   = (const float*)d_in[9];
    const float* bin_  = (const float*)d_in[10];
    const float* Whn   = (const float*)d_in[11];
    const float* bhn   = (const float*)d_in[12];
    const float* Wh    = (const float*)d_in[13];
    const float* bh    = (const float*)d_in[14];
    const float* Wo    = (const float*)d_in[15];
    const float* bo    = (const float*)d_in[16];
    float* out = (float*)d_out;

    void *pY = 0, *pWc = 0, *pbc = 0;
    cudaGetSymbolAddress(&pY,  g_y);
    cudaGetSymbolAddress(&pWc, g_Wc);
    cudaGetSymbolAddress(&pbc, g_bc);

    cudaFuncSetAttribute(scan_kernel, cudaFuncAttributeMaxDynamicSharedMemorySize, SCAN_SMEM);

    prep_ew<<<128, 256>>>(emb, Wir, bir, Wiz, biz, Win, bin_);
    gemm128<<<8, 256>>>(Wh, Wo, (const float*)0, (float*)pWc);   // Wc = Wh @ Wo
    prep_misc<<<65, 256>>>(carry, bh, Wo, bo);
    scan_kernel<<<NCTA, 512, SCAN_SMEM>>>(toks, Whr, Whz, Whn, bhn);
    copy_carry<<<64, 256>>>(out);
    gemm128<<<256, 256>>>((const float*)pY, (const float*)pWc, (const float*)pbc,
                          out + 65536);                           // logits
}